// round 3
// baseline (speedup 1.0000x reference)
#include <cuda_runtime.h>
#include <math.h>

#define NG 50000
#define ND 25000
#define CH 128
#define NH 4
#define E1N 150000
#define E2N 150000
#define FG 512
#define FD 256

// ---------------- scratch (device globals; no allocation) ----------------
__device__ float    d_g[(size_t)NG * CH];        // gene features (evolving)
__device__ float    d_xs[(size_t)NG * 512];      // xs = x_src @ Ws  (max 50000x512)
__device__ float    d_ls[NG * NH];               // per-src attention term
__device__ float    d_ldv[NG * NH];              // per-dst attention term
__device__ unsigned d_mkey[NG * NH];             // segment max (monotone uint key)
__device__ float    d_den[NG * NH];              // segment softmax denom
__device__ float    d_pe[(size_t)(E2N + NG) * NH]; // per-edge logits, then p
__device__ float    d_stats[2 * CH];             // BN col sum / sumsq
__device__ float    d_aff[2 * CH];               // BN scale / shift
__device__ float    d_fold[CH * NH];             // folded Wd @ a_d

// ---------------- helpers ----------------
__device__ __forceinline__ unsigned fkey(float f) {
    unsigned u = __float_as_uint(f);
    return (u & 0x80000000u) ? ~u : (u | 0x80000000u);
}
__device__ __forceinline__ float fkinv(unsigned k) {
    return (k & 0x80000000u) ? __uint_as_float(k ^ 0x80000000u)
                             : __uint_as_float(~k);
}

// ---------------- SGEMM: C = [relu](A[M,K] @ B[K,N] (+ bias)) ----------------
// BM=BN=128, BK=16, 256 threads, 8x8 micro-tile with stride-16 layout.
template<bool RELU, bool BIAS>
__global__ void sgemm_k(const float* __restrict__ A, const float* __restrict__ B,
                        const float* __restrict__ bias, float* __restrict__ Cout,
                        int M, int N, int K)
{
    __shared__ float As[128 * 20];
    __shared__ float Bs[16 * 128];
    const int t  = threadIdx.x;
    const int tx = t & 15, ty = t >> 4;
    const int row0 = blockIdx.y * 128, col0 = blockIdx.x * 128;

    float acc[8][8];
#pragma unroll
    for (int i = 0; i < 8; i++)
#pragma unroll
        for (int j = 0; j < 8; j++) acc[i][j] = 0.f;

    for (int kt = 0; kt < K; kt += 16) {
#pragma unroll
        for (int u = 0; u < 2; u++) {
            int f  = t * 2 + u;
            int r  = f >> 2;            // 0..127
            int kk = (f & 3) * 4;
            float4 v = make_float4(0.f, 0.f, 0.f, 0.f);
            int gr = row0 + r;
            if (gr < M) v = *(const float4*)(A + (size_t)gr * K + kt + kk);
            *(float4*)(As + r * 20 + kk) = v;
        }
#pragma unroll
        for (int u = 0; u < 2; u++) {
            int f  = t * 2 + u;
            int kk = f >> 5;            // 0..15
            int cc = (f & 31) * 4;      // 0..124
            float4 v = *(const float4*)(B + (size_t)(kt + kk) * N + col0 + cc);
            *(float4*)(Bs + kk * 128 + cc) = v;
        }
        __syncthreads();
#pragma unroll
        for (int k = 0; k < 16; k++) {
            float ra[8], rb[8];
#pragma unroll
            for (int i = 0; i < 8; i++) ra[i] = As[(ty + i * 16) * 20 + k];
#pragma unroll
            for (int j = 0; j < 8; j++) rb[j] = Bs[k * 128 + tx + j * 16];
#pragma unroll
            for (int i = 0; i < 8; i++)
#pragma unroll
                for (int j = 0; j < 8; j++) acc[i][j] += ra[i] * rb[j];
        }
        __syncthreads();
    }

#pragma unroll
    for (int i = 0; i < 8; i++) {
        int gr = row0 + ty + i * 16;
        if (gr >= M) continue;
#pragma unroll
        for (int j = 0; j < 8; j++) {
            int gc  = col0 + tx + j * 16;
            float v = acc[i][j];
            if (BIAS) v += bias[gc & (CH - 1)];
            if (RELU) v = fmaxf(v, 0.f);
            Cout[(size_t)gr * N + gc] = v;
        }
    }
}

// ---------------- BatchNorm ----------------
__global__ void zero_stats_k() { d_stats[threadIdx.x] = 0.f; }

__global__ void bn_stats_k(const float* __restrict__ h, int M) {
    int c = threadIdx.x;   // 128 threads
    int per = (M + gridDim.x - 1) / gridDim.x;
    int r0 = blockIdx.x * per;
    int r1 = r0 + per; if (r1 > M) r1 = M;
    float s = 0.f, ss = 0.f;
    for (int r = r0; r < r1; r++) {
        float v = h[(size_t)r * CH + c];
        s += v; ss += v * v;
    }
    atomicAdd(&d_stats[c], s);
    atomicAdd(&d_stats[CH + c], ss);
}

__global__ void bn_final_k(const float* __restrict__ gamma, const float* __restrict__ beta,
                           float invM) {
    int c = threadIdx.x;
    float mu  = d_stats[c] * invM;
    float var = d_stats[CH + c] * invM - mu * mu;
    float a = gamma[c] * rsqrtf(var + 1e-5f);
    d_aff[c] = a;
    d_aff[CH + c] = beta[c] - mu * a;
}

__global__ void bn_apply_k(float* __restrict__ h, int M) {
    int idx = blockIdx.x * blockDim.x + threadIdx.x;
    if (idx < M * CH) {
        int c = idx & (CH - 1);
        h[idx] = h[idx] * d_aff[c] + d_aff[CH + c];
    }
}

// ---------------- fold Wd with a_d: fold[i,h] = sum_c Wd[i, h*CH+c] * a_d[h,c] ----------------
__global__ void fold_k(const float* __restrict__ W, const float* __restrict__ a) {
    int t = threadIdx.x;          // 512 threads
    int i = t >> 2, h = t & 3;
    float s = 0.f;
    for (int c = 0; c < CH; c++)
        s += W[(size_t)i * (NH * CH) + h * CH + c] * a[h * CH + c];
    d_fold[i * NH + h] = s;
}

// ---------------- ls[n,h] = sum_c xs[n, h*CH+c] * a_s[h,c]  (warp per (n,h)) ----------------
__global__ void ls_k(const float* __restrict__ xs, const float* __restrict__ a, int N) {
    int w = (blockIdx.x * blockDim.x + threadIdx.x) >> 5;
    int lane = threadIdx.x & 31;
    if (w >= N * NH) return;
    int n = w >> 2, h = w & 3;
    const float* xp = xs + (size_t)n * (NH * CH) + h * CH;
    const float* ap = a + h * CH;
    float s = 0.f;
    for (int c = lane; c < CH; c += 32) s += xp[c] * ap[c];
    for (int o = 16; o; o >>= 1) s += __shfl_down_sync(0xffffffffu, s, o);
    if (!lane) d_ls[w] = s;
}

// ---------------- ld[n,h] = sum_i g[n,i] * fold[i,h]  (warp per (n,h)) ----------------
__global__ void ld_k(const float* __restrict__ g, int N) {
    int w = (blockIdx.x * blockDim.x + threadIdx.x) >> 5;
    int lane = threadIdx.x & 31;
    if (w >= N * NH) return;
    int n = w >> 2, h = w & 3;
    const float* gp = g + (size_t)n * CH;
    float s = 0.f;
    for (int c = lane; c < CH; c += 32) s += gp[c] * d_fold[c * NH + h];
    for (int o = 16; o; o >>= 1) s += __shfl_down_sync(0xffffffffu, s, o);
    if (!lane) d_ldv[w] = s;
}

// ---------------- edge passes ----------------
__global__ void einit_k(int N) {
    int i = blockIdx.x * blockDim.x + threadIdx.x;
    if (i < N * NH) { d_mkey[i] = 0x007FFFFFu; /* key(-inf) */ d_den[i] = 0.f; }
}

__global__ void passA_k(const int* __restrict__ src, const int* __restrict__ dst,
                        int E, int nloop) {
    int tid = blockIdx.x * blockDim.x + threadIdx.x;
    if (tid >= (E + nloop) * NH) return;
    int e = tid >> 2, h = tid & 3;
    int s, d; bool mask;
    if (e < E) { s = src[e]; d = dst[e]; mask = (s != d); }
    else       { s = d = e - E; mask = true; }
    float x = d_ls[s * NH + h] + d_ldv[d * NH + h];
    x = x > 0.f ? x : 0.2f * x;                 // leaky_relu(0.2)
    if (!mask) x = -1e30f;
    d_pe[tid] = x;
    atomicMax(&d_mkey[d * NH + h], fkey(x));
}

__global__ void passB_k(const int* __restrict__ src, const int* __restrict__ dst,
                        int E, int nloop) {
    int tid = blockIdx.x * blockDim.x + threadIdx.x;
    if (tid >= (E + nloop) * NH) return;
    int e = tid >> 2, h = tid & 3;
    int s, d; bool mask;
    if (e < E) { s = src[e]; d = dst[e]; mask = (s != d); }
    else       { s = d = e - E; mask = true; }
    float x = d_pe[tid];
    float m = fkinv(d_mkey[d * NH + h]);
    if (isinf(m)) m = 0.f;                      // empty-segment fill
    float p = mask ? expf(x - m) : 0.f;
    d_pe[tid] = p;
    if (p != 0.f) atomicAdd(&d_den[d * NH + h], p);
}

__global__ void addb_k(float* __restrict__ o, const float* __restrict__ b, int M) {
    int idx = blockIdx.x * blockDim.x + threadIdx.x;
    if (idx < M * CH) o[idx] += b[idx & (CH - 1)];
}

__global__ void initout_k(float* __restrict__ o, const float* __restrict__ g,
                          const float* __restrict__ b, int M) {
    int idx = blockIdx.x * blockDim.x + threadIdx.x;
    if (idx < M * CH) o[idx] = g[idx] + b[idx & (CH - 1)];
}

// thread per (edge, channel)
__global__ void passC_k(const int* __restrict__ src, const int* __restrict__ dst,
                        int E, int nloop, float* __restrict__ out) {
    long long tid = (long long)blockIdx.x * blockDim.x + threadIdx.x;
    long long tot = (long long)(E + nloop) * CH;
    if (tid >= tot) return;
    int e = (int)(tid >> 7), c = (int)(tid & 127);
    int s, d;
    if (e < E) { s = __ldg(src + e); d = __ldg(dst + e); if (s == d) return; }
    else       { s = d = e - E; }
    const float* xp = d_xs + (size_t)s * (NH * CH) + c;
    float acc = 0.f;
#pragma unroll
    for (int h = 0; h < NH; h++) {
        float den = __ldg(&d_den[d * NH + h]);
        den = den > 0.f ? den : 1.f;
        float al = __ldg(&d_pe[(size_t)e * NH + h]) / den;
        acc += al * xp[h * CH];
    }
    if (acc != 0.f) atomicAdd(&out[(size_t)d * CH + c], 0.25f * acc);
}

// ---------------- host ----------------
extern "C" void kernel_launch(void* const* d_in, const int* in_sizes, int n_in,
                              void* d_out, int out_size) {
    const float* x_gene = (const float*)d_in[0];
    const float* x_dis  = (const float*)d_in[1];
    const int*   e1s    = (const int*)d_in[2];
    const int*   e1d    = (const int*)d_in[3];
    const int*   e2s    = (const int*)d_in[4];
    const int*   e2d    = (const int*)d_in[5];
    const float* Wg = (const float*)d_in[6],  *bg = (const float*)d_in[7];
    const float* gg = (const float*)d_in[8],  *betag = (const float*)d_in[9];
    const float* Wd = (const float*)d_in[10], *bd = (const float*)d_in[11];
    const float* gd = (const float*)d_in[12], *betad = (const float*)d_in[13];
    const float* W1s = (const float*)d_in[14], *W1d = (const float*)d_in[15];
    const float* a1s = (const float*)d_in[16], *a1d = (const float*)d_in[17];
    const float* b1  = (const float*)d_in[18];
    const float* W2s = (const float*)d_in[19], *W2d = (const float*)d_in[20];
    const float* a2s = (const float*)d_in[21], *a2d = (const float*)d_in[22];
    const float* b2  = (const float*)d_in[23];

    float* outg = (float*)d_out;
    float* outd = outg + (size_t)NG * CH;

    float *pg = nullptr, *pxs = nullptr;
    cudaGetSymbolAddress((void**)&pg,  d_g);
    cudaGetSymbolAddress((void**)&pxs, d_xs);

    const int TB = 256;
    // ---- encode gene ----
    zero_stats_k<<<1, 256>>>();
    sgemm_k<true, true><<<dim3(1, (NG + 127) / 128), TB>>>(x_gene, Wg, bg, pg, NG, CH, FG);
    bn_stats_k<<<128, 128>>>(pg, NG);
    bn_final_k<<<1, 128>>>(gg, betag, 1.f / NG);
    bn_apply_k<<<(NG * CH + TB - 1) / TB, TB>>>(pg, NG);
    // ---- encode dis (directly into output region) ----
    zero_stats_k<<<1, 256>>>();
    sgemm_k<true, true><<<dim3(1, (ND + 127) / 128), TB>>>(x_dis, Wd, bd, outd, ND, CH, FD);
    bn_stats_k<<<128, 128>>>(outd, ND);
    bn_final_k<<<1, 128>>>(gd, betad, 1.f / ND);
    bn_apply_k<<<(ND * CH + TB - 1) / TB, TB>>>(outd, ND);

    // ---- relation 1: dis -> gene ----
    fold_k<<<1, 512>>>(W1d, a1d);
    sgemm_k<false, false><<<dim3(4, (ND + 127) / 128), TB>>>(outd, W1s, nullptr, pxs, ND, NH * CH, CH);
    ls_k<<<(ND * NH * 32 + TB - 1) / TB, TB>>>(pxs, a1s, ND);
    ld_k<<<(NG * NH * 32 + TB - 1) / TB, TB>>>(pg, NG);
    einit_k<<<(NG * NH + TB - 1) / TB, TB>>>(NG);
    int tot1 = E1N + ND;
    passA_k<<<(tot1 * NH + TB - 1) / TB, TB>>>(e1s, e1d, E1N, ND);
    passB_k<<<(tot1 * NH + TB - 1) / TB, TB>>>(e1s, e1d, E1N, ND);
    addb_k<<<(NG * CH + TB - 1) / TB, TB>>>(pg, b1, NG);           // gene += b1, then scatter on top
    passC_k<<<(int)(((long long)tot1 * CH + TB - 1) / TB), TB>>>(e1s, e1d, E1N, ND, pg);

    // ---- relation 2: gene -> gene ----
    fold_k<<<1, 512>>>(W2d, a2d);
    sgemm_k<false, false><<<dim3(4, (NG + 127) / 128), TB>>>(pg, W2s, nullptr, pxs, NG, NH * CH, CH);
    ls_k<<<(NG * NH * 32 + TB - 1) / TB, TB>>>(pxs, a2s, NG);
    ld_k<<<(NG * NH * 32 + TB - 1) / TB, TB>>>(pg, NG);
    einit_k<<<(NG * NH + TB - 1) / TB, TB>>>(NG);
    int tot2 = E2N + NG;
    passA_k<<<(tot2 * NH + TB - 1) / TB, TB>>>(e2s, e2d, E2N, NG);
    passB_k<<<(tot2 * NH + TB - 1) / TB, TB>>>(e2s, e2d, E2N, NG);
    initout_k<<<(NG * CH + TB - 1) / TB, TB>>>(outg, pg, b2, NG);  // out = gene1 + b2
    passC_k<<<(int)(((long long)tot2 * CH + TB - 1) / TB), TB>>>(e2s, e2d, E2N, NG, outg);
}

// round 6
// speedup vs baseline: 1.0587x; 1.0587x over previous
#include <cuda_runtime.h>
#include <math.h>

#define NG 50000
#define ND 25000
#define CH 128
#define NH 4
#define E1N 150000
#define E2N 150000
#define FG 512
#define FD 256

// ---------------- scratch (device globals; no allocation) ----------------
__device__ float    d_g[(size_t)NG * CH];        // gene features (evolving)
__device__ float    d_xs[(size_t)NG * 512];      // xs = x_src @ Ws  (max 50000x512)
__device__ float    d_ls[NG * NH];               // per-src attention term
__device__ float    d_ldv[NG * NH];              // per-dst attention term
__device__ unsigned d_mkey[NG * NH];             // segment max (monotone uint key)
__device__ float    d_den[NG * NH];              // segment softmax denom
__device__ float    d_pe[(size_t)(E2N + NG) * NH]; // per-edge logits, then p
__device__ float    d_stats[2 * CH];             // BN col sum / sumsq
__device__ float    d_aff[2 * CH];               // BN scale / shift
__device__ float    d_fold[CH * NH];             // folded Wd @ a_d

// ---------------- helpers ----------------
__device__ __forceinline__ unsigned fkey(float f) {
    unsigned u = __float_as_uint(f);
    return (u & 0x80000000u) ? ~u : (u | 0x80000000u);
}
__device__ __forceinline__ float fkinv(unsigned k) {
    return (k & 0x80000000u) ? __uint_as_float(k ^ 0x80000000u)
                             : __uint_as_float(~k);
}
__device__ __forceinline__ unsigned f2tf32(float f) {
    unsigned r;
    asm("cvt.rna.tf32.f32 %0, %1;" : "=r"(r) : "f"(f));
    return r;
}
__device__ __forceinline__ void mma_tf32(float* c, const unsigned* a, const unsigned* b) {
    asm volatile(
        "mma.sync.aligned.m16n8k8.row.col.f32.tf32.tf32.f32 "
        "{%0,%1,%2,%3}, {%4,%5,%6,%7}, {%8,%9}, {%0,%1,%2,%3};\n"
        : "+f"(c[0]), "+f"(c[1]), "+f"(c[2]), "+f"(c[3])
        : "r"(a[0]), "r"(a[1]), "r"(a[2]), "r"(a[3]), "r"(b[0]), "r"(b[1]));
}

// ---------------- TF32 tensor-core GEMM: C = [relu](A[M,K] @ B[K,N] (+ bias)) ----
// Block tile 128x64, BK=16, 256 threads (8 warps, 4x2), warp tile 32x32.
// SMEM holds pre-permuted mma fragments: A frag via LDS.128, B frag via LDS.64.
template<bool RELU, bool BIAS>
__global__ void __launch_bounds__(256) mma_gemm_k(
    const float* __restrict__ A, const float* __restrict__ B,
    const float* __restrict__ bias, float* __restrict__ Cout,
    int M, int N, int K)
{
    // [mt(8)][ks(2)][lane*4+slot]  /  [nt(8)][ks(2)][lane*2+slot]
    __shared__ unsigned smA[8 * 2 * 128];
    __shared__ unsigned smB[8 * 2 * 64];

    const int t    = threadIdx.x;
    const int lane = t & 31;
    const int w    = t >> 5;
    const int wr   = w >> 1;           // 0..3  (rows)
    const int wc   = w & 1;            // 0..1  (cols)
    const int row0 = blockIdx.y * 128;
    const int col0 = blockIdx.x * 64;

    float acc[2][4][4];
#pragma unroll
    for (int i = 0; i < 2; i++)
#pragma unroll
        for (int j = 0; j < 4; j++)
#pragma unroll
            for (int q = 0; q < 4; q++) acc[i][j][q] = 0.f;

    // Loader geometry
    const int arow = t >> 1;                 // 0..127
    const int akb  = (t & 1) * 8;            // 0 or 8
    const int bk   = t >> 4;                 // 0..15
    const int bc   = (t & 15) * 4;           // 0..60

    float4 pa0, pa1, pb;

    // prefetch tile 0
    {
        int gr = row0 + arow;
        if (gr < M) {
            const float* p = A + (size_t)gr * K + akb;
            pa0 = *(const float4*)p;
            pa1 = *(const float4*)(p + 4);
        } else {
            pa0 = pa1 = make_float4(0.f, 0.f, 0.f, 0.f);
        }
        pb = *(const float4*)(B + (size_t)bk * N + col0 + bc);
    }

    for (int kt = 0; kt < K; kt += 16) {
        // ---- store prefetched tile to permuted smem ----
        {
            float av[8] = {pa0.x, pa0.y, pa0.z, pa0.w, pa1.x, pa1.y, pa1.z, pa1.w};
            int mt = arow >> 4;
            int ks = t & 1;                  // akb>>3
            unsigned* base = smA + (mt * 2 + ks) * 128;
#pragma unroll
            for (int j = 0; j < 8; j++) {
                int k    = akb + j;          // k within BK tile
                int slot = ((arow >> 3) & 1) + 2 * ((j >> 2) & 1);
                int ln   = ((arow & 7) << 2) | (k & 3);
                base[ln * 4 + slot] = f2tf32(av[j]);
            }
            float bv[4] = {pb.x, pb.y, pb.z, pb.w};
            int ksb  = bk >> 3;
            int slot = (bk >> 2) & 1;
#pragma unroll
            for (int j = 0; j < 4; j++) {
                int n  = bc + j;
                int nt = n >> 3;
                int ln = ((n & 7) << 2) | (bk & 3);
                smB[(nt * 2 + ksb) * 64 + ln * 2 + slot] = f2tf32(bv[j]);
            }
        }
        __syncthreads();

        // ---- prefetch next tile ----
        if (kt + 16 < K) {
            int gr = row0 + arow;
            if (gr < M) {
                const float* p = A + (size_t)gr * K + kt + 16 + akb;
                pa0 = *(const float4*)p;
                pa1 = *(const float4*)(p + 4);
            } else {
                pa0 = pa1 = make_float4(0.f, 0.f, 0.f, 0.f);
            }
            pb = *(const float4*)(B + (size_t)(kt + 16 + bk) * N + col0 + bc);
        }

        // ---- compute both k-steps ----
#pragma unroll
        for (int ks = 0; ks < 2; ks++) {
            unsigned afr[2][4];
#pragma unroll
            for (int i = 0; i < 2; i++)
                *(uint4*)afr[i] =
                    *(const uint4*)&smA[((wr * 2 + i) * 2 + ks) * 128 + lane * 4];
            unsigned bfr[4][2];
#pragma unroll
            for (int j = 0; j < 4; j++)
                *(uint2*)bfr[j] =
                    *(const uint2*)&smB[((wc * 4 + j) * 2 + ks) * 64 + lane * 2];
#pragma unroll
            for (int i = 0; i < 2; i++)
#pragma unroll
                for (int j = 0; j < 4; j++) mma_tf32(acc[i][j], afr[i], bfr[j]);
        }
        __syncthreads();
    }

    // ---- epilogue ----
#pragma unroll
    for (int i = 0; i < 2; i++) {
        int mr = row0 + wr * 32 + i * 16 + (lane >> 2);
#pragma unroll
        for (int j = 0; j < 4; j++) {
            int nc = col0 + wc * 32 + j * 8 + (lane & 3) * 2;
#pragma unroll
            for (int half = 0; half < 2; half++) {
                int gr = mr + half * 8;
                if (gr >= M) continue;
#pragma unroll
                for (int q = 0; q < 2; q++) {
                    int gc = nc + q;
                    float v = acc[i][j][half * 2 + q];
                    if (BIAS) v += bias[gc & (CH - 1)];
                    if (RELU) v = fmaxf(v, 0.f);
                    Cout[(size_t)gr * N + gc] = v;
                }
            }
        }
    }
}

// ---------------- BatchNorm ----------------
__global__ void zero_stats_k() { d_stats[threadIdx.x] = 0.f; }

__global__ void bn_stats_k(const float* __restrict__ h, int M) {
    int c = threadIdx.x;   // 128 threads
    int per = (M + gridDim.x - 1) / gridDim.x;
    int r0 = blockIdx.x * per;
    int r1 = r0 + per; if (r1 > M) r1 = M;
    float s = 0.f, ss = 0.f;
    for (int r = r0; r < r1; r++) {
        float v = h[(size_t)r * CH + c];
        s += v; ss += v * v;
    }
    atomicAdd(&d_stats[c], s);
    atomicAdd(&d_stats[CH + c], ss);
}

__global__ void bn_final_k(const float* __restrict__ gamma, const float* __restrict__ beta,
                           float invM) {
    int c = threadIdx.x;
    float mu  = d_stats[c] * invM;
    float var = d_stats[CH + c] * invM - mu * mu;
    float a = gamma[c] * rsqrtf(var + 1e-5f);
    d_aff[c] = a;
    d_aff[CH + c] = beta[c] - mu * a;
}

__global__ void bn_apply_k(float* __restrict__ h, int M) {
    int idx = blockIdx.x * blockDim.x + threadIdx.x;
    if (idx < M * CH) {
        int c = idx & (CH - 1);
        h[idx] = h[idx] * d_aff[c] + d_aff[CH + c];
    }
}

// ---------------- fold Wd with a_d: fold[i,h] = sum_c Wd[i, h*CH+c] * a_d[h,c] ----------------
__global__ void fold_k(const float* __restrict__ W, const float* __restrict__ a) {
    int t = threadIdx.x;          // 512 threads
    int i = t >> 2, h = t & 3;
    float s = 0.f;
    for (int c = 0; c < CH; c++)
        s += W[(size_t)i * (NH * CH) + h * CH + c] * a[h * CH + c];
    d_fold[i * NH + h] = s;
}

// ---------------- ls[n,h] = sum_c xs[n, h*CH+c] * a_s[h,c]  (warp per (n,h)) ----------------
__global__ void ls_k(const float* __restrict__ xs, const float* __restrict__ a, int N) {
    int w = (blockIdx.x * blockDim.x + threadIdx.x) >> 5;
    int lane = threadIdx.x & 31;
    if (w >= N * NH) return;
    int n = w >> 2, h = w & 3;
    const float* xp = xs + (size_t)n * (NH * CH) + h * CH;
    const float* ap = a + h * CH;
    float s = 0.f;
    for (int c = lane; c < CH; c += 32) s += xp[c] * ap[c];
    for (int o = 16; o; o >>= 1) s += __shfl_down_sync(0xffffffffu, s, o);
    if (!lane) d_ls[w] = s;
}

// ---------------- ld[n,h] = sum_i g[n,i] * fold[i,h]  (warp per (n,h)) ----------------
__global__ void ld_k(const float* __restrict__ g, int N) {
    int w = (blockIdx.x * blockDim.x + threadIdx.x) >> 5;
    int lane = threadIdx.x & 31;
    if (w >= N * NH) return;
    int n = w >> 2, h = w & 3;
    const float* gp = g + (size_t)n * CH;
    float s = 0.f;
    for (int c = lane; c < CH; c += 32) s += gp[c] * d_fold[c * NH + h];
    for (int o = 16; o; o >>= 1) s += __shfl_down_sync(0xffffffffu, s, o);
    if (!lane) d_ldv[w] = s;
}

// ---------------- edge passes ----------------
__global__ void einit_k(int N) {
    int i = blockIdx.x * blockDim.x + threadIdx.x;
    if (i < N * NH) { d_mkey[i] = 0x007FFFFFu; /* key(-inf) */ d_den[i] = 0.f; }
}

__global__ void passA_k(const int* __restrict__ src, const int* __restrict__ dst,
                        int E, int nloop) {
    int tid = blockIdx.x * blockDim.x + threadIdx.x;
    if (tid >= (E + nloop) * NH) return;
    int e = tid >> 2, h = tid & 3;
    int s, d; bool mask;
    if (e < E) { s = src[e]; d = dst[e]; mask = (s != d); }
    else       { s = d = e - E; mask = true; }
    float x = d_ls[s * NH + h] + d_ldv[d * NH + h];
    x = x > 0.f ? x : 0.2f * x;                 // leaky_relu(0.2)
    if (!mask) x = -1e30f;
    d_pe[tid] = x;
    atomicMax(&d_mkey[d * NH + h], fkey(x));
}

__global__ void passB_k(const int* __restrict__ src, const int* __restrict__ dst,
                        int E, int nloop) {
    int tid = blockIdx.x * blockDim.x + threadIdx.x;
    if (tid >= (E + nloop) * NH) return;
    int e = tid >> 2, h = tid & 3;
    int s, d; bool mask;
    if (e < E) { s = src[e]; d = dst[e]; mask = (s != d); }
    else       { s = d = e - E; mask = true; }
    float x = d_pe[tid];
    float m = fkinv(d_mkey[d * NH + h]);
    if (isinf(m)) m = 0.f;                      // empty-segment fill
    float p = mask ? expf(x - m) : 0.f;
    d_pe[tid] = p;
    if (p != 0.f) atomicAdd(&d_den[d * NH + h], p);
}

__global__ void addb_k(float* __restrict__ o, const float* __restrict__ b, int M) {
    int idx = blockIdx.x * blockDim.x + threadIdx.x;
    if (idx < M * CH) o[idx] += b[idx & (CH - 1)];
}

__global__ void initout_k(float* __restrict__ o, const float* __restrict__ g,
                          const float* __restrict__ b, int M) {
    int idx = blockIdx.x * blockDim.x + threadIdx.x;
    if (idx < M * CH) o[idx] = g[idx] + b[idx & (CH - 1)];
}

// thread per (edge, channel)
__global__ void passC_k(const int* __restrict__ src, const int* __restrict__ dst,
                        int E, int nloop, float* __restrict__ out) {
    long long tid = (long long)blockIdx.x * blockDim.x + threadIdx.x;
    long long tot = (long long)(E + nloop) * CH;
    if (tid >= tot) return;
    int e = (int)(tid >> 7), c = (int)(tid & 127);
    int s, d;
    if (e < E) { s = __ldg(src + e); d = __ldg(dst + e); if (s == d) return; }
    else       { s = d = e - E; }
    const float* xp = d_xs + (size_t)s * (NH * CH) + c;
    float acc = 0.f;
#pragma unroll
    for (int h = 0; h < NH; h++) {
        float den = __ldg(&d_den[d * NH + h]);
        den = den > 0.f ? den : 1.f;
        float al = __ldg(&d_pe[(size_t)e * NH + h]) / den;
        acc += al * xp[h * CH];
    }
    if (acc != 0.f) atomicAdd(&out[(size_t)d * CH + c], 0.25f * acc);
}

// ---------------- host ----------------
extern "C" void kernel_launch(void* const* d_in, const int* in_sizes, int n_in,
                              void* d_out, int out_size) {
    const float* x_gene = (const float*)d_in[0];
    const float* x_dis  = (const float*)d_in[1];
    const int*   e1s    = (const int*)d_in[2];
    const int*   e1d    = (const int*)d_in[3];
    const int*   e2s    = (const int*)d_in[4];
    const int*   e2d    = (const int*)d_in[5];
    const float* Wg = (const float*)d_in[6],  *bg = (const float*)d_in[7];
    const float* gg = (const float*)d_in[8],  *betag = (const float*)d_in[9];
    const float* Wd = (const float*)d_in[10], *bd = (const float*)d_in[11];
    const float* gd = (const float*)d_in[12], *betad = (const float*)d_in[13];
    const float* W1s = (const float*)d_in[14], *W1d = (const float*)d_in[15];
    const float* a1s = (const float*)d_in[16], *a1d = (const float*)d_in[17];
    const float* b1  = (const float*)d_in[18];
    const float* W2s = (const float*)d_in[19], *W2d = (const float*)d_in[20];
    const float* a2s = (const float*)d_in[21], *a2d = (const float*)d_in[22];
    const float* b2  = (const float*)d_in[23];

    float* outg = (float*)d_out;
    float* outd = outg + (size_t)NG * CH;

    float *pg = nullptr, *pxs = nullptr;
    cudaGetSymbolAddress((void**)&pg,  d_g);
    cudaGetSymbolAddress((void**)&pxs, d_xs);

    const int TB = 256;
    // ---- encode gene ----
    zero_stats_k<<<1, 256>>>();
    mma_gemm_k<true, true><<<dim3(CH / 64, (NG + 127) / 128), 256>>>(x_gene, Wg, bg, pg, NG, CH, FG);
    bn_stats_k<<<128, 128>>>(pg, NG);
    bn_final_k<<<1, 128>>>(gg, betag, 1.f / NG);
    bn_apply_k<<<(NG * CH + TB - 1) / TB, TB>>>(pg, NG);
    // ---- encode dis (directly into output region) ----
    zero_stats_k<<<1, 256>>>();
    mma_gemm_k<true, true><<<dim3(CH / 64, (ND + 127) / 128), 256>>>(x_dis, Wd, bd, outd, ND, CH, FD);
    bn_stats_k<<<128, 128>>>(outd, ND);
    bn_final_k<<<1, 128>>>(gd, betad, 1.f / ND);
    bn_apply_k<<<(ND * CH + TB - 1) / TB, TB>>>(outd, ND);

    // ---- relation 1: dis -> gene ----
    fold_k<<<1, 512>>>(W1d, a1d);
    mma_gemm_k<false, false><<<dim3((NH * CH) / 64, (ND + 127) / 128), 256>>>(outd, W1s, nullptr, pxs, ND, NH * CH, CH);
    ls_k<<<(ND * NH * 32 + TB - 1) / TB, TB>>>(pxs, a1s, ND);
    ld_k<<<(NG * NH * 32 + TB - 1) / TB, TB>>>(pg, NG);
    einit_k<<<(NG * NH + TB - 1) / TB, TB>>>(NG);
    int tot1 = E1N + ND;
    passA_k<<<(tot1 * NH + TB - 1) / TB, TB>>>(e1s, e1d, E1N, ND);
    passB_k<<<(tot1 * NH + TB - 1) / TB, TB>>>(e1s, e1d, E1N, ND);
    addb_k<<<(NG * CH + TB - 1) / TB, TB>>>(pg, b1, NG);           // gene += b1, then scatter on top
    passC_k<<<(int)(((long long)tot1 * CH + TB - 1) / TB), TB>>>(e1s, e1d, E1N, ND, pg);

    // ---- relation 2: gene -> gene ----
    fold_k<<<1, 512>>>(W2d, a2d);
    mma_gemm_k<false, false><<<dim3((NH * CH) / 64, (NG + 127) / 128), 256>>>(pg, W2s, nullptr, pxs, NG, NH * CH, CH);
    ls_k<<<(NG * NH * 32 + TB - 1) / TB, TB>>>(pxs, a2s, NG);
    ld_k<<<(NG * NH * 32 + TB - 1) / TB, TB>>>(pg, NG);
    einit_k<<<(NG * NH + TB - 1) / TB, TB>>>(NG);
    int tot2 = E2N + NG;
    passA_k<<<(tot2 * NH + TB - 1) / TB, TB>>>(e2s, e2d, E2N, NG);
    passB_k<<<(tot2 * NH + TB - 1) / TB, TB>>>(e2s, e2d, E2N, NG);
    initout_k<<<(NG * CH + TB - 1) / TB, TB>>>(outg, pg, b2, NG);  // out = gene1 + b2
    passC_k<<<(int)(((long long)tot2 * CH + TB - 1) / TB), TB>>>(e2s, e2d, E2N, NG, outg);
}

// round 13
// speedup vs baseline: 1.4249x; 1.3459x over previous
#include <cuda_runtime.h>
#include <cuda_fp16.h>
#include <math.h>

#define NG 50000
#define ND 25000
#define CH 128
#define NH 4
#define E1N 150000
#define E2N 150000
#define FG 512
#define FD 256

// ---------------- scratch (device globals; no allocation) ----------------
__device__ float    d_g[(size_t)NG * CH];        // gene features (evolving)
__device__ float    d_xs[(size_t)NG * 512];      // xs = x_src @ Ws  (max 50000x512)
__device__ float    d_ls[NG * NH];               // per-src attention term
__device__ float    d_ldv[NG * NH];              // per-dst attention term
__device__ unsigned d_mkey[NG * NH];             // segment max (monotone uint key)
__device__ float    d_den[NG * NH];              // segment softmax denom
__device__ float    d_pe[(size_t)(E2N + NG) * NH]; // per-edge logits, then p
__device__ float    d_stats[2 * CH];             // BN col sum / sumsq
__device__ float    d_aff[2 * CH];               // BN scale / shift
__device__ float    d_fold[CH * NH];             // folded Wd @ a_d

// ---------------- helpers ----------------
__device__ __forceinline__ unsigned fkey(float f) {
    unsigned u = __float_as_uint(f);
    return (u & 0x80000000u) ? ~u : (u | 0x80000000u);
}
__device__ __forceinline__ float fkinv(unsigned k) {
    return (k & 0x80000000u) ? __uint_as_float(k ^ 0x80000000u)
                             : __uint_as_float(~k);
}
__device__ __forceinline__ unsigned smem_u32(const void* p) {
    unsigned a;
    asm("{ .reg .u64 t; cvta.to.shared.u64 t, %1; cvt.u32.u64 %0, t; }"
        : "=r"(a) : "l"(p));
    return a;
}
__device__ __forceinline__ void ldsm4(unsigned* r, unsigned addr) {
    asm volatile("ldmatrix.sync.aligned.m8n8.x4.shared.b16 {%0,%1,%2,%3}, [%4];"
                 : "=r"(r[0]), "=r"(r[1]), "=r"(r[2]), "=r"(r[3]) : "r"(addr));
}
__device__ __forceinline__ void mma16816(float* c, const unsigned* a, const unsigned* b) {
    asm volatile(
        "mma.sync.aligned.m16n8k16.row.col.f32.f16.f16.f32 "
        "{%0,%1,%2,%3},{%4,%5,%6,%7},{%8,%9},{%0,%1,%2,%3};"
        : "+f"(c[0]), "+f"(c[1]), "+f"(c[2]), "+f"(c[3])
        : "r"(a[0]), "r"(a[1]), "r"(a[2]), "r"(a[3]), "r"(b[0]), "r"(b[1]));
}

// ---------------- fp16 tensor-core GEMM: C = [relu](A[M,K] @ B[K,N] (+ bias)) ----
// CTA tile 128x128, BK=32, 256 threads (8 warps 4x2), warp tile 32x64.
// SMEM rows padded to 40 halfs (80B) -> conflict-free LDSM. fp32->fp16 on fill.
#define LDPAD 40

template<bool RELU, bool BIAS>
__global__ void __launch_bounds__(256, 2) hgemm_k(
    const float* __restrict__ A, const float* __restrict__ B,
    const float* __restrict__ bias, float* __restrict__ Cout,
    int M, int N, int K)
{
    __shared__ __half smA[128 * LDPAD];
    __shared__ __half smB[128 * LDPAD];

    const int t = threadIdx.x;
    const int lane = t & 31;
    const int w = t >> 5;
    const int wr = w >> 1;            // 0..3
    const int wc = w & 1;             // 0..1
    const int row0 = blockIdx.y * 128, col0 = blockIdx.x * 128;

    float acc[2][8][4];
#pragma unroll
    for (int i = 0; i < 2; i++)
#pragma unroll
        for (int j = 0; j < 8; j++)
#pragma unroll
            for (int q = 0; q < 4; q++) acc[i][j][q] = 0.f;

    const unsigned baseA = smem_u32(smA);
    const unsigned baseB = smem_u32(smB);

    // LDSM per-lane geometry
    const int arow_off = ((lane >> 3) & 1) * 8 + (lane & 7);  // within 16-row frag
    const int achunk   = lane >> 4;                            // 0/1
    const int brow_off = ((lane >> 4) & 1) * 8 + (lane & 7);
    const int bchunk   = (lane >> 3) & 1;

    float4 pa[4], pb[4];
    // prefetch tile 0
#pragma unroll
    for (int rep = 0; rep < 4; rep++) {
        int i = t + rep * 256;
        int r = i >> 3, kq = (i & 7) << 2;
        int gr = row0 + r;
        pa[rep] = (gr < M) ? *(const float4*)(A + (size_t)gr * K + kq)
                           : make_float4(0.f, 0.f, 0.f, 0.f);
        int kk = i & 31, nb = (i >> 5) << 2;
        pb[rep] = *(const float4*)(B + (size_t)kk * N + col0 + nb);
    }

    for (int kt = 0; kt < K; kt += 32) {
        // ---- store prefetched tile ----
#pragma unroll
        for (int rep = 0; rep < 4; rep++) {
            int i = t + rep * 256;
            int r = i >> 3, kq = (i & 7) << 2;
            __half2 h0 = __floats2half2_rn(pa[rep].x, pa[rep].y);
            __half2 h1 = __floats2half2_rn(pa[rep].z, pa[rep].w);
            *(__half2*)(smA + r * LDPAD + kq)     = h0;
            *(__half2*)(smA + r * LDPAD + kq + 2) = h1;
            int kk = i & 31, nb = (i >> 5) << 2;
            float vv[4] = {pb[rep].x, pb[rep].y, pb[rep].z, pb[rep].w};
#pragma unroll
            for (int j = 0; j < 4; j++)
                smB[(nb + j) * LDPAD + kk] = __float2half_rn(vv[j]);
        }
        __syncthreads();

        // ---- prefetch next ----
        if (kt + 32 < K) {
#pragma unroll
            for (int rep = 0; rep < 4; rep++) {
                int i = t + rep * 256;
                int r = i >> 3, kq = (i & 7) << 2;
                int gr = row0 + r;
                pa[rep] = (gr < M) ? *(const float4*)(A + (size_t)gr * K + kt + 32 + kq)
                                   : make_float4(0.f, 0.f, 0.f, 0.f);
                int kk = i & 31, nb = (i >> 5) << 2;
                pb[rep] = *(const float4*)(B + (size_t)(kt + 32 + kk) * N + col0 + nb);
            }
        }

        // ---- compute 2 k16 steps ----
#pragma unroll
        for (int ks = 0; ks < 2; ks++) {
            unsigned af[2][4];
#pragma unroll
            for (int i = 0; i < 2; i++) {
                int row = wr * 32 + i * 16 + arow_off;
                unsigned addr = baseA + (unsigned)(row * LDPAD + (2 * ks + achunk) * 8) * 2u;
                ldsm4(af[i], addr);
            }
            unsigned bf[4][4];
#pragma unroll
            for (int j2 = 0; j2 < 4; j2++) {
                int row = wc * 64 + j2 * 16 + brow_off;
                unsigned addr = baseB + (unsigned)(row * LDPAD + (2 * ks + bchunk) * 8) * 2u;
                ldsm4(bf[j2], addr);
            }
#pragma unroll
            for (int i = 0; i < 2; i++)
#pragma unroll
                for (int j = 0; j < 8; j++)
                    mma16816(acc[i][j], af[i], &bf[j >> 1][(j & 1) * 2]);
        }
        __syncthreads();
    }

    // ---- epilogue ----
#pragma unroll
    for (int i = 0; i < 2; i++) {
        int mr = row0 + wr * 32 + i * 16 + (lane >> 2);
#pragma unroll
        for (int j = 0; j < 8; j++) {
            int gc = col0 + wc * 64 + j * 8 + (lane & 3) * 2;
#pragma unroll
            for (int half = 0; half < 2; half++) {
                int gr = mr + half * 8;
                if (gr >= M) continue;
                float v0 = acc[i][j][half * 2 + 0];
                float v1 = acc[i][j][half * 2 + 1];
                if (BIAS) { v0 += bias[gc & (CH - 1)]; v1 += bias[(gc + 1) & (CH - 1)]; }
                if (RELU) { v0 = fmaxf(v0, 0.f); v1 = fmaxf(v1, 0.f); }
                *(float2*)(Cout + (size_t)gr * N + gc) = make_float2(v0, v1);
            }
        }
    }
}

// ---------------- BatchNorm ----------------
__global__ void zero_stats_k() {
    int i = blockIdx.x * blockDim.x + threadIdx.x;
    if (i < 2 * CH) d_stats[i] = 0.f;
}

__global__ void bn_stats_k(const float* __restrict__ h, int M) {
    int c = threadIdx.x;   // 128 threads
    int per = (M + gridDim.x - 1) / gridDim.x;
    int r0 = blockIdx.x * per;
    int r1 = r0 + per; if (r1 > M) r1 = M;
    float s = 0.f, ss = 0.f;
    for (int r = r0; r < r1; r++) {
        float v = h[(size_t)r * CH + c];
        s += v; ss += v * v;
    }
    atomicAdd(&d_stats[c], s);
    atomicAdd(&d_stats[CH + c], ss);
}

__global__ void bn_final_k(const float* __restrict__ gamma, const float* __restrict__ beta,
                           float invM) {
    int c = threadIdx.x;
    float mu  = d_stats[c] * invM;
    float var = d_stats[CH + c] * invM - mu * mu;
    float a = gamma[c] * rsqrtf(var + 1e-5f);
    d_aff[c] = a;
    d_aff[CH + c] = beta[c] - mu * a;
}

__global__ void bn_apply_k(float* __restrict__ h, int M) {
    int idx = blockIdx.x * blockDim.x + threadIdx.x;
    if (idx < M * CH) {
        int c = idx & (CH - 1);
        h[idx] = h[idx] * d_aff[c] + d_aff[CH + c];
    }
}

// ---------------- fold Wd with a_d ----------------
__global__ void fold_k(const float* __restrict__ W, const float* __restrict__ a) {
    int t = threadIdx.x;          // 512 threads
    int i = t >> 2, h = t & 3;
    float s = 0.f;
    for (int c = 0; c < CH; c++)
        s += W[(size_t)i * (NH * CH) + h * CH + c] * a[h * CH + c];
    d_fold[i * NH + h] = s;
}

// ---------------- ls[n,h] = sum_c xs[n, h*CH+c] * a_s[h,c] ----------------
__global__ void ls_k(const float* __restrict__ xs, const float* __restrict__ a, int N) {
    int w = (blockIdx.x * blockDim.x + threadIdx.x) >> 5;
    int lane = threadIdx.x & 31;
    if (w >= N * NH) return;
    int n = w >> 2, h = w & 3;
    const float* xp = xs + (size_t)n * (NH * CH) + h * CH;
    const float* ap = a + h * CH;
    float s = 0.f;
    for (int c = lane; c < CH; c += 32) s += xp[c] * ap[c];
    for (int o = 16; o; o >>= 1) s += __shfl_down_sync(0xffffffffu, s, o);
    if (!lane) d_ls[w] = s;
}

// ---------------- ld[n,h] = sum_i g[n,i] * fold[i,h] ----------------
__global__ void ld_k(const float* __restrict__ g, int N) {
    int w = (blockIdx.x * blockDim.x + threadIdx.x) >> 5;
    int lane = threadIdx.x & 31;
    if (w >= N * NH) return;
    int n = w >> 2, h = w & 3;
    const float* gp = g + (size_t)n * CH;
    float s = 0.f;
    for (int c = lane; c < CH; c += 32) s += gp[c] * d_fold[c * NH + h];
    for (int o = 16; o; o >>= 1) s += __shfl_down_sync(0xffffffffu, s, o);
    if (!lane) d_ldv[w] = s;
}

// ---------------- edge passes ----------------
__global__ void einit_k(int N) {
    int i = blockIdx.x * blockDim.x + threadIdx.x;
    if (i < N * NH) { d_mkey[i] = 0x007FFFFFu; /* key(-inf) */ d_den[i] = 0.f; }
}

__global__ void passA_k(const int* __restrict__ src, const int* __restrict__ dst,
                        int E, int nloop) {
    int tid = blockIdx.x * blockDim.x + threadIdx.x;
    if (tid >= (E + nloop) * NH) return;
    int e = tid >> 2, h = tid & 3;
    int s, d; bool mask;
    if (e < E) { s = src[e]; d = dst[e]; mask = (s != d); }
    else       { s = d = e - E; mask = true; }
    float x = d_ls[s * NH + h] + d_ldv[d * NH + h];
    x = x > 0.f ? x : 0.2f * x;                 // leaky_relu(0.2)
    if (!mask) x = -1e30f;
    d_pe[tid] = x;
    atomicMax(&d_mkey[d * NH + h], fkey(x));
}

__global__ void passB_k(const int* __restrict__ src, const int* __restrict__ dst,
                        int E, int nloop) {
    int tid = blockIdx.x * blockDim.x + threadIdx.x;
    if (tid >= (E + nloop) * NH) return;
    int e = tid >> 2, h = tid & 3;
    int s, d; bool mask;
    if (e < E) { s = src[e]; d = dst[e]; mask = (s != d); }
    else       { s = d = e - E; mask = true; }
    float x = d_pe[tid];
    float m = fkinv(d_mkey[d * NH + h]);
    if (isinf(m)) m = 0.f;                      // empty-segment fill
    float p = mask ? expf(x - m) : 0.f;
    d_pe[tid] = p;
    if (p != 0.f) atomicAdd(&d_den[d * NH + h], p);
}

__global__ void addb_k(float* __restrict__ o, const float* __restrict__ b, int M) {
    int idx = blockIdx.x * blockDim.x + threadIdx.x;
    if (idx < M * CH) o[idx] += b[idx & (CH - 1)];
}

__global__ void initout_k(float* __restrict__ o, const float* __restrict__ g,
                          const float* __restrict__ b, int M) {
    int idx = blockIdx.x * blockDim.x + threadIdx.x;
    if (idx < M * CH) o[idx] = g[idx] + b[idx & (CH - 1)];
}

// thread per (edge, channel)
__global__ void passC_k(const int* __restrict__ src, const int* __restrict__ dst,
                        int E, int nloop, float* __restrict__ out) {
    long long tid = (long long)blockIdx.x * blockDim.x + threadIdx.x;
    long long tot = (long long)(E + nloop) * CH;
    if (tid >= tot) return;
    int e = (int)(tid >> 7), c = (int)(tid & 127);
    int s, d;
    if (e < E) { s = __ldg(src + e); d = __ldg(dst + e); if (s == d) return; }
    else       { s = d = e - E; }
    const float* xp = d_xs + (size_t)s * (NH * CH) + c;
    float acc = 0.f;
#pragma unroll
    for (int h = 0; h < NH; h++) {
        float den = __ldg(&d_den[d * NH + h]);
        den = den > 0.f ? den : 1.f;
        float al = __ldg(&d_pe[(size_t)e * NH + h]) / den;
        acc += al * xp[h * CH];
    }
    if (acc != 0.f) atomicAdd(&out[(size_t)d * CH + c], 0.25f * acc);
}

// ---------------- host ----------------
extern "C" void kernel_launch(void* const* d_in, const int* in_sizes, int n_in,
                              void* d_out, int out_size) {
    const float* x_gene = (const float*)d_in[0];
    const float* x_dis  = (const float*)d_in[1];
    const int*   e1s    = (const int*)d_in[2];
    const int*   e1d    = (const int*)d_in[3];
    const int*   e2s    = (const int*)d_in[4];
    const int*   e2d    = (const int*)d_in[5];
    const float* Wg = (const float*)d_in[6],  *bg = (const float*)d_in[7];
    const float* gg = (const float*)d_in[8],  *betag = (const float*)d_in[9];
    const float* Wd = (const float*)d_in[10], *bd = (const float*)d_in[11];
    const float* gd = (const float*)d_in[12], *betad = (const float*)d_in[13];
    const float* W1s = (const float*)d_in[14], *W1d = (const float*)d_in[15];
    const float* a1s = (const float*)d_in[16], *a1d = (const float*)d_in[17];
    const float* b1  = (const float*)d_in[18];
    const float* W2s = (const float*)d_in[19], *W2d = (const float*)d_in[20];
    const float* a2s = (const float*)d_in[21], *a2d = (const float*)d_in[22];
    const float* b2  = (const float*)d_in[23];

    float* outg = (float*)d_out;
    float* outd = outg + (size_t)NG * CH;

    float *pg = nullptr, *pxs = nullptr;
    cudaGetSymbolAddress((void**)&pg,  d_g);
    cudaGetSymbolAddress((void**)&pxs, d_xs);

    const int TB = 256;
    // ---- encode gene ----
    zero_stats_k<<<1, 256>>>();
    hgemm_k<true, true><<<dim3(1, (NG + 127) / 128), 256>>>(x_gene, Wg, bg, pg, NG, CH, FG);
    bn_stats_k<<<128, 128>>>(pg, NG);
    bn_final_k<<<1, 128>>>(gg, betag, 1.f / NG);
    bn_apply_k<<<(NG * CH + TB - 1) / TB, TB>>>(pg, NG);
    // ---- encode dis (directly into output region) ----
    zero_stats_k<<<1, 256>>>();
    hgemm_k<true, true><<<dim3(1, (ND + 127) / 128), 256>>>(x_dis, Wd, bd, outd, ND, CH, FD);
    bn_stats_k<<<128, 128>>>(outd, ND);
    bn_final_k<<<1, 128>>>(gd, betad, 1.f / ND);
    bn_apply_k<<<(ND * CH + TB - 1) / TB, TB>>>(outd, ND);

    // ---- relation 1: dis -> gene ----
    fold_k<<<1, 512>>>(W1d, a1d);
    hgemm_k<false, false><<<dim3((NH * CH) / 128, (ND + 127) / 128), 256>>>(outd, W1s, nullptr, pxs, ND, NH * CH, CH);
    ls_k<<<(ND * NH * 32 + TB - 1) / TB, TB>>>(pxs, a1s, ND);
    ld_k<<<(NG * NH * 32 + TB - 1) / TB, TB>>>(pg, NG);
    einit_k<<<(NG * NH + TB - 1) / TB, TB>>>(NG);
    int tot1 = E1N + ND;
    passA_k<<<(tot1 * NH + TB - 1) / TB, TB>>>(e1s, e1d, E1N, ND);
    passB_k<<<(tot1 * NH + TB - 1) / TB, TB>>>(e1s, e1d, E1N, ND);
    addb_k<<<(NG * CH + TB - 1) / TB, TB>>>(pg, b1, NG);           // gene += b1, then scatter on top
    passC_k<<<(int)(((long long)tot1 * CH + TB - 1) / TB), TB>>>(e1s, e1d, E1N, ND, pg);

    // ---- relation 2: gene -> gene ----
    fold_k<<<1, 512>>>(W2d, a2d);
    hgemm_k<false, false><<<dim3((NH * CH) / 128, (NG + 127) / 128), 256>>>(pg, W2s, nullptr, pxs, NG, NH * CH, CH);
    ls_k<<<(NG * NH * 32 + TB - 1) / TB, TB>>>(pxs, a2s, NG);
    ld_k<<<(NG * NH * 32 + TB - 1) / TB, TB>>>(pg, NG);
    einit_k<<<(NG * NH + TB - 1) / TB, TB>>>(NG);
    int tot2 = E2N + NG;
    passA_k<<<(tot2 * NH + TB - 1) / TB, TB>>>(e2s, e2d, E2N, NG);
    passB_k<<<(tot2 * NH + TB - 1) / TB, TB>>>(e2s, e2d, E2N, NG);
    initout_k<<<(NG * CH + TB - 1) / TB, TB>>>(outg, pg, b2, NG);  // out = gene1 + b2
    passC_k<<<(int)(((long long)tot2 * CH + TB - 1) / TB), TB>>>(e2s, e2d, E2N, NG, outg);
}

// round 14
// speedup vs baseline: 1.7236x; 1.2096x over previous
#include <cuda_runtime.h>
#include <cuda_fp16.h>
#include <math.h>

#define NG 50000
#define ND 25000
#define CH 128
#define NH 4
#define E1N 150000
#define E2N 150000
#define FG 512
#define FD 256

// ---------------- scratch (device globals; no allocation) ----------------
__device__ float    d_g[(size_t)NG * CH];        // gene features (evolving)
__device__ float    d_xs[(size_t)NG * 512];      // xs = x_src @ Ws  (max 50000x512)
__device__ float    d_ls[NG * NH];               // per-src attention term
__device__ float    d_ldv[NG * NH];              // per-dst attention term
__device__ float    d_stats[2 * CH];             // BN col sum / sumsq
__device__ float    d_aff[2 * CH];               // BN scale / shift
__device__ float    d_fold[CH * NH];             // folded Wd @ a_d
__device__ int      d_cnt[NG];                   // CSR degree counts
__device__ int      d_cur[NG];                   // CSR scatter cursors
__device__ int      d_off[NG + 1];               // CSR offsets
__device__ int      d_eid[E2N + NG];             // CSR edge ids

// ---------------- helpers ----------------
__device__ __forceinline__ unsigned smem_u32(const void* p) {
    unsigned a;
    asm("{ .reg .u64 t; cvta.to.shared.u64 t, %1; cvt.u32.u64 %0, t; }"
        : "=r"(a) : "l"(p));
    return a;
}
__device__ __forceinline__ void ldsm4(unsigned* r, unsigned addr) {
    asm volatile("ldmatrix.sync.aligned.m8n8.x4.shared.b16 {%0,%1,%2,%3}, [%4];"
                 : "=r"(r[0]), "=r"(r[1]), "=r"(r[2]), "=r"(r[3]) : "r"(addr));
}
__device__ __forceinline__ void mma16816(float* c, const unsigned* a, const unsigned* b) {
    asm volatile(
        "mma.sync.aligned.m16n8k16.row.col.f32.f16.f16.f32 "
        "{%0,%1,%2,%3},{%4,%5,%6,%7},{%8,%9},{%0,%1,%2,%3};"
        : "+f"(c[0]), "+f"(c[1]), "+f"(c[2]), "+f"(c[3])
        : "r"(a[0]), "r"(a[1]), "r"(a[2]), "r"(a[3]), "r"(b[0]), "r"(b[1]));
}

// ---------------- fp16 tensor-core GEMM: C = [relu](A[M,K] @ B[K,N] (+ bias)) ----
// CTA tile 128x128, BK=32, 256 threads (8 warps 4x2), warp tile 32x64.
// SMEM rows padded to 40 halfs (80B) -> conflict-free LDSM. fp32->fp16 on fill.
#define LDPAD 40

template<bool RELU, bool BIAS>
__global__ void __launch_bounds__(256, 2) hgemm_k(
    const float* __restrict__ A, const float* __restrict__ B,
    const float* __restrict__ bias, float* __restrict__ Cout,
    int M, int N, int K)
{
    __shared__ __half smA[128 * LDPAD];
    __shared__ __half smB[128 * LDPAD];

    const int t = threadIdx.x;
    const int lane = t & 31;
    const int w = t >> 5;
    const int wr = w >> 1;            // 0..3
    const int wc = w & 1;             // 0..1
    const int row0 = blockIdx.y * 128, col0 = blockIdx.x * 128;

    float acc[2][8][4];
#pragma unroll
    for (int i = 0; i < 2; i++)
#pragma unroll
        for (int j = 0; j < 8; j++)
#pragma unroll
            for (int q = 0; q < 4; q++) acc[i][j][q] = 0.f;

    const unsigned baseA = smem_u32(smA);
    const unsigned baseB = smem_u32(smB);

    // LDSM per-lane geometry
    const int arow_off = ((lane >> 3) & 1) * 8 + (lane & 7);  // within 16-row frag
    const int achunk   = lane >> 4;                            // 0/1
    const int brow_off = ((lane >> 4) & 1) * 8 + (lane & 7);
    const int bchunk   = (lane >> 3) & 1;

    float4 pa[4], pb[4];
    // prefetch tile 0
#pragma unroll
    for (int rep = 0; rep < 4; rep++) {
        int i = t + rep * 256;
        int r = i >> 3, kq = (i & 7) << 2;
        int gr = row0 + r;
        pa[rep] = (gr < M) ? *(const float4*)(A + (size_t)gr * K + kq)
                           : make_float4(0.f, 0.f, 0.f, 0.f);
        int kk = i & 31, nb = (i >> 5) << 2;
        pb[rep] = *(const float4*)(B + (size_t)kk * N + col0 + nb);
    }

    for (int kt = 0; kt < K; kt += 32) {
        // ---- store prefetched tile ----
#pragma unroll
        for (int rep = 0; rep < 4; rep++) {
            int i = t + rep * 256;
            int r = i >> 3, kq = (i & 7) << 2;
            __half2 h0 = __floats2half2_rn(pa[rep].x, pa[rep].y);
            __half2 h1 = __floats2half2_rn(pa[rep].z, pa[rep].w);
            *(__half2*)(smA + r * LDPAD + kq)     = h0;
            *(__half2*)(smA + r * LDPAD + kq + 2) = h1;
            int kk = i & 31, nb = (i >> 5) << 2;
            float vv[4] = {pb[rep].x, pb[rep].y, pb[rep].z, pb[rep].w};
#pragma unroll
            for (int j = 0; j < 4; j++)
                smB[(nb + j) * LDPAD + kk] = __float2half_rn(vv[j]);
        }
        __syncthreads();

        // ---- prefetch next ----
        if (kt + 32 < K) {
#pragma unroll
            for (int rep = 0; rep < 4; rep++) {
                int i = t + rep * 256;
                int r = i >> 3, kq = (i & 7) << 2;
                int gr = row0 + r;
                pa[rep] = (gr < M) ? *(const float4*)(A + (size_t)gr * K + kt + 32 + kq)
                                   : make_float4(0.f, 0.f, 0.f, 0.f);
                int kk = i & 31, nb = (i >> 5) << 2;
                pb[rep] = *(const float4*)(B + (size_t)(kt + 32 + kk) * N + col0 + nb);
            }
        }

        // ---- compute 2 k16 steps ----
#pragma unroll
        for (int ks = 0; ks < 2; ks++) {
            unsigned af[2][4];
#pragma unroll
            for (int i = 0; i < 2; i++) {
                int row = wr * 32 + i * 16 + arow_off;
                unsigned addr = baseA + (unsigned)(row * LDPAD + (2 * ks + achunk) * 8) * 2u;
                ldsm4(af[i], addr);
            }
            unsigned bf[4][4];
#pragma unroll
            for (int j2 = 0; j2 < 4; j2++) {
                int row = wc * 64 + j2 * 16 + brow_off;
                unsigned addr = baseB + (unsigned)(row * LDPAD + (2 * ks + bchunk) * 8) * 2u;
                ldsm4(bf[j2], addr);
            }
#pragma unroll
            for (int i = 0; i < 2; i++)
#pragma unroll
                for (int j = 0; j < 8; j++)
                    mma16816(acc[i][j], af[i], &bf[j >> 1][(j & 1) * 2]);
        }
        __syncthreads();
    }

    // ---- epilogue ----
#pragma unroll
    for (int i = 0; i < 2; i++) {
        int mr = row0 + wr * 32 + i * 16 + (lane >> 2);
#pragma unroll
        for (int j = 0; j < 8; j++) {
            int gc = col0 + wc * 64 + j * 8 + (lane & 3) * 2;
#pragma unroll
            for (int half = 0; half < 2; half++) {
                int gr = mr + half * 8;
                if (gr >= M) continue;
                float v0 = acc[i][j][half * 2 + 0];
                float v1 = acc[i][j][half * 2 + 1];
                if (BIAS) { v0 += bias[gc & (CH - 1)]; v1 += bias[(gc + 1) & (CH - 1)]; }
                if (RELU) { v0 = fmaxf(v0, 0.f); v1 = fmaxf(v1, 0.f); }
                *(float2*)(Cout + (size_t)gr * N + gc) = make_float2(v0, v1);
            }
        }
    }
}

// ---------------- BatchNorm ----------------
__global__ void zero_stats_k() {
    int i = blockIdx.x * blockDim.x + threadIdx.x;
    if (i < 2 * CH) d_stats[i] = 0.f;
}

__global__ void bn_stats_k(const float* __restrict__ h, int M) {
    int c = threadIdx.x;   // 128 threads
    int per = (M + gridDim.x - 1) / gridDim.x;
    int r0 = blockIdx.x * per;
    int r1 = r0 + per; if (r1 > M) r1 = M;
    float s = 0.f, ss = 0.f;
    for (int r = r0; r < r1; r++) {
        float v = h[(size_t)r * CH + c];
        s += v; ss += v * v;
    }
    atomicAdd(&d_stats[c], s);
    atomicAdd(&d_stats[CH + c], ss);
}

__global__ void bn_final_k(const float* __restrict__ gamma, const float* __restrict__ beta,
                           float invM) {
    int c = threadIdx.x;
    float mu  = d_stats[c] * invM;
    float var = d_stats[CH + c] * invM - mu * mu;
    float a = gamma[c] * rsqrtf(var + 1e-5f);
    d_aff[c] = a;
    d_aff[CH + c] = beta[c] - mu * a;
}

__global__ void bn_apply_k(float* __restrict__ h, int M) {
    int idx = blockIdx.x * blockDim.x + threadIdx.x;
    if (idx < M * CH) {
        int c = idx & (CH - 1);
        h[idx] = h[idx] * d_aff[c] + d_aff[CH + c];
    }
}

// ---------------- fold Wd with a_d ----------------
__global__ void fold_k(const float* __restrict__ W, const float* __restrict__ a) {
    int t = threadIdx.x;          // 512 threads
    int i = t >> 2, h = t & 3;
    float s = 0.f;
    for (int c = 0; c < CH; c++)
        s += W[(size_t)i * (NH * CH) + h * CH + c] * a[h * CH + c];
    d_fold[i * NH + h] = s;
}

// ---------------- ls[n,h] = sum_c xs[n, h*CH+c] * a_s[h,c] ----------------
__global__ void ls_k(const float* __restrict__ xs, const float* __restrict__ a, int N) {
    int w = (blockIdx.x * blockDim.x + threadIdx.x) >> 5;
    int lane = threadIdx.x & 31;
    if (w >= N * NH) return;
    int n = w >> 2, h = w & 3;
    const float* xp = xs + (size_t)n * (NH * CH) + h * CH;
    const float* ap = a + h * CH;
    float s = 0.f;
    for (int c = lane; c < CH; c += 32) s += xp[c] * ap[c];
    for (int o = 16; o; o >>= 1) s += __shfl_down_sync(0xffffffffu, s, o);
    if (!lane) d_ls[w] = s;
}

// ---------------- ld[n,h] = sum_i g[n,i] * fold[i,h] ----------------
__global__ void ld_k(const float* __restrict__ g, int N) {
    int w = (blockIdx.x * blockDim.x + threadIdx.x) >> 5;
    int lane = threadIdx.x & 31;
    if (w >= N * NH) return;
    int n = w >> 2, h = w & 3;
    const float* gp = g + (size_t)n * CH;
    float s = 0.f;
    for (int c = lane; c < CH; c += 32) s += gp[c] * d_fold[c * NH + h];
    for (int o = 16; o; o >>= 1) s += __shfl_down_sync(0xffffffffu, s, o);
    if (!lane) d_ldv[w] = s;
}

// ---------------- CSR build ----------------
__global__ void initcsr_k() {
    int i = blockIdx.x * blockDim.x + threadIdx.x;
    if (i < NG) { d_cnt[i] = 0; d_cur[i] = 0; }
}

__global__ void hist_k(const int* __restrict__ src, const int* __restrict__ dst,
                       int E, int nloop) {
    int e = blockIdx.x * blockDim.x + threadIdx.x;
    if (e >= E + nloop) return;
    int d;
    if (e < E) {
        int s = src[e]; d = dst[e];
        if (s == d) return;                  // masked (remove_self_loops)
    } else d = e - E;
    atomicAdd(&d_cnt[d], 1);
}

// exclusive scan of d_cnt[0..NG) into d_off; d_off[NG] = total. One block, 1024 thr.
__global__ void scan_k() {
    __shared__ int ps[1024];
    int t = threadIdx.x;
    const int per = (NG + 1023) / 1024;
    int s0 = t * per, s1 = s0 + per; if (s1 > NG) s1 = NG; if (s0 > NG) s0 = NG;
    int sum = 0;
    for (int i = s0; i < s1; i++) sum += d_cnt[i];
    ps[t] = sum;
    __syncthreads();
    for (int o = 1; o < 1024; o <<= 1) {
        int v = (t >= o) ? ps[t - o] : 0;
        __syncthreads();
        ps[t] += v;
        __syncthreads();
    }
    int run = (t > 0) ? ps[t - 1] : 0;
    for (int i = s0; i < s1; i++) { d_off[i] = run; run += d_cnt[i]; }
    if (t == 1023) d_off[NG] = ps[1023];
}

__global__ void scatter_k(const int* __restrict__ src, const int* __restrict__ dst,
                          int E, int nloop) {
    int e = blockIdx.x * blockDim.x + threadIdx.x;
    if (e >= E + nloop) return;
    int d;
    if (e < E) {
        int s = src[e]; d = dst[e];
        if (s == d) return;
    } else d = e - E;
    int pos = atomicAdd(&d_cur[d], 1);
    d_eid[d_off[d] + pos] = e;
}

// ---------------- gather: warp per dst. out = base + bias + mean_h softmax-agg ----
__global__ void __launch_bounds__(256) gather_k(
    const int* __restrict__ src, int E,
    const float* __restrict__ base, const float* __restrict__ bias,
    float* __restrict__ out)
{
    int w = (blockIdx.x * blockDim.x + threadIdx.x) >> 5;
    int lane = threadIdx.x & 31;
    if (w >= NG) return;
    int o0 = d_off[w], o1 = d_off[w + 1];

    float ldh = (lane < 4) ? d_ldv[w * 4 + lane] : 0.f;

    // pass 1: per-head max of leaky_relu(ls+ld) over segment
    float mx = -1e30f;
    for (int i = o0; i < o1; i++) {
        int e = d_eid[i];
        int s = (e < E) ? src[e] : (e - E);
        if (lane < 4) {
            float x = d_ls[s * 4 + lane] + ldh;
            x = x > 0.f ? x : 0.2f * x;
            mx = fmaxf(mx, x);
        }
    }

    // pass 2: accumulate exp weights and weighted xs
    float4 a0 = make_float4(0.f,0.f,0.f,0.f), a1 = a0, a2 = a0, a3 = a0;
    float den = 0.f;
    for (int i = o0; i < o1; i++) {
        int e = d_eid[i];
        int s = (e < E) ? src[e] : (e - E);
        float p = 0.f;
        if (lane < 4) {
            float x = d_ls[s * 4 + lane] + ldh;
            x = x > 0.f ? x : 0.2f * x;
            p = expf(x - mx);
            den += p;
        }
        float p0 = __shfl_sync(0xffffffffu, p, 0);
        float p1 = __shfl_sync(0xffffffffu, p, 1);
        float p2 = __shfl_sync(0xffffffffu, p, 2);
        float p3 = __shfl_sync(0xffffffffu, p, 3);
        const float4* xp = (const float4*)(d_xs + (size_t)s * 512);
        float4 v;
        v = xp[lane];      a0.x += p0*v.x; a0.y += p0*v.y; a0.z += p0*v.z; a0.w += p0*v.w;
        v = xp[32 + lane]; a1.x += p1*v.x; a1.y += p1*v.y; a1.z += p1*v.z; a1.w += p1*v.w;
        v = xp[64 + lane]; a2.x += p2*v.x; a2.y += p2*v.y; a2.z += p2*v.z; a2.w += p2*v.w;
        v = xp[96 + lane]; a3.x += p3*v.x; a3.y += p3*v.y; a3.z += p3*v.z; a3.w += p3*v.w;
    }
    float d0 = __shfl_sync(0xffffffffu, den, 0);
    float d1 = __shfl_sync(0xffffffffu, den, 1);
    float d2 = __shfl_sync(0xffffffffu, den, 2);
    float d3 = __shfl_sync(0xffffffffu, den, 3);
    float i0 = (d0 > 0.f) ? 0.25f / d0 : 0.25f;
    float i1 = (d1 > 0.f) ? 0.25f / d1 : 0.25f;
    float i2 = (d2 > 0.f) ? 0.25f / d2 : 0.25f;
    float i3 = (d3 > 0.f) ? 0.25f / d3 : 0.25f;

    size_t idx = (size_t)w * CH + lane * 4;
    float4 bs = *(const float4*)(bias + lane * 4);
    float4 bv = *(const float4*)(base + idx);
    float4 r;
    r.x = bv.x + bs.x + a0.x*i0 + a1.x*i1 + a2.x*i2 + a3.x*i3;
    r.y = bv.y + bs.y + a0.y*i0 + a1.y*i1 + a2.y*i2 + a3.y*i3;
    r.z = bv.z + bs.z + a0.z*i0 + a1.z*i1 + a2.z*i2 + a3.z*i3;
    r.w = bv.w + bs.w + a0.w*i0 + a1.w*i1 + a2.w*i2 + a3.w*i3;
    *(float4*)(out + idx) = r;
}

// ---------------- host ----------------
extern "C" void kernel_launch(void* const* d_in, const int* in_sizes, int n_in,
                              void* d_out, int out_size) {
    const float* x_gene = (const float*)d_in[0];
    const float* x_dis  = (const float*)d_in[1];
    const int*   e1s    = (const int*)d_in[2];
    const int*   e1d    = (const int*)d_in[3];
    const int*   e2s    = (const int*)d_in[4];
    const int*   e2d    = (const int*)d_in[5];
    const float* Wg = (const float*)d_in[6],  *bg = (const float*)d_in[7];
    const float* gg = (const float*)d_in[8],  *betag = (const float*)d_in[9];
    const float* Wd = (const float*)d_in[10], *bd = (const float*)d_in[11];
    const float* gd = (const float*)d_in[12], *betad = (const float*)d_in[13];
    const float* W1s = (const float*)d_in[14], *W1d = (const float*)d_in[15];
    const float* a1s = (const float*)d_in[16], *a1d = (const float*)d_in[17];
    const float* b1  = (const float*)d_in[18];
    const float* W2s = (const float*)d_in[19], *W2d = (const float*)d_in[20];
    const float* a2s = (const float*)d_in[21], *a2d = (const float*)d_in[22];
    const float* b2  = (const float*)d_in[23];

    float* outg = (float*)d_out;
    float* outd = outg + (size_t)NG * CH;

    float *pg = nullptr, *pxs = nullptr;
    cudaGetSymbolAddress((void**)&pg,  d_g);
    cudaGetSymbolAddress((void**)&pxs, d_xs);

    const int TB = 256;
    // ---- encode gene ----
    zero_stats_k<<<1, 256>>>();
    hgemm_k<true, true><<<dim3(1, (NG + 127) / 128), 256>>>(x_gene, Wg, bg, pg, NG, CH, FG);
    bn_stats_k<<<128, 128>>>(pg, NG);
    bn_final_k<<<1, 128>>>(gg, betag, 1.f / NG);
    bn_apply_k<<<(NG * CH + TB - 1) / TB, TB>>>(pg, NG);
    // ---- encode dis (directly into output region) ----
    zero_stats_k<<<1, 256>>>();
    hgemm_k<true, true><<<dim3(1, (ND + 127) / 128), 256>>>(x_dis, Wd, bd, outd, ND, CH, FD);
    bn_stats_k<<<128, 128>>>(outd, ND);
    bn_final_k<<<1, 128>>>(gd, betad, 1.f / ND);
    bn_apply_k<<<(ND * CH + TB - 1) / TB, TB>>>(outd, ND);

    // ---- relation 1: dis -> gene (in-place update of pg) ----
    fold_k<<<1, 512>>>(W1d, a1d);
    hgemm_k<false, false><<<dim3((NH * CH) / 128, (ND + 127) / 128), 256>>>(outd, W1s, nullptr, pxs, ND, NH * CH, CH);
    ls_k<<<(ND * NH * 32 + TB - 1) / TB, TB>>>(pxs, a1s, ND);
    ld_k<<<(NG * NH * 32 + TB - 1) / TB, TB>>>(pg, NG);
    initcsr_k<<<(NG + TB - 1) / TB, TB>>>();
    int tot1 = E1N + ND;
    hist_k<<<(tot1 + TB - 1) / TB, TB>>>(e1s, e1d, E1N, ND);
    scan_k<<<1, 1024>>>();
    scatter_k<<<(tot1 + TB - 1) / TB, TB>>>(e1s, e1d, E1N, ND);
    gather_k<<<(NG * 32 + TB - 1) / TB, TB>>>(e1s, E1N, pg, b1, pg);

    // ---- relation 2: gene -> gene (writes final outg) ----
    fold_k<<<1, 512>>>(W2d, a2d);
    hgemm_k<false, false><<<dim3((NH * CH) / 128, (NG + 127) / 128), 256>>>(pg, W2s, nullptr, pxs, NG, NH * CH, CH);
    ls_k<<<(NG * NH * 32 + TB - 1) / TB, TB>>>(pxs, a2s, NG);
    ld_k<<<(NG * NH * 32 + TB - 1) / TB, TB>>>(pg, NG);
    initcsr_k<<<(NG + TB - 1) / TB, TB>>>();
    int tot2 = E2N + NG;
    hist_k<<<(tot2 + TB - 1) / TB, TB>>>(e2s, e2d, E2N, NG);
    scan_k<<<1, 1024>>>();
    scatter_k<<<(tot2 + TB - 1) / TB, TB>>>(e2s, e2d, E2N, NG);
    gather_k<<<(NG * 32 + TB - 1) / TB, TB>>>(e2s, E2N, pg, b2, outg);
}

// round 15
// speedup vs baseline: 2.0572x; 1.1936x over previous
#include <cuda_runtime.h>
#include <cuda_fp16.h>
#include <math.h>

#define NG 50000
#define ND 25000
#define CH 128
#define NH 4
#define E1N 150000
#define E2N 150000
#define FG 512
#define FD 256

// ---------------- scratch (device globals; no allocation) ----------------
__device__ float    d_g[(size_t)NG * CH];        // gene features (evolving)
__device__ float    d_xs[(size_t)NG * 512];      // xs = x_src @ Ws  (max 50000x512)
__device__ float    d_ls[NG * NH];               // per-src attention term
__device__ float    d_ldv[NG * NH];              // per-dst attention term
__device__ float    d_stats[2 * CH];             // BN col sum / sumsq
__device__ float    d_aff[2 * CH];               // BN scale / shift
__device__ float    d_fold[CH * NH];             // folded Wd @ a_d
__device__ int      d_cnt[NG];                   // CSR degree counts
__device__ int      d_cur[NG];                   // CSR scatter cursors
__device__ int      d_off[NG + 1];               // CSR offsets
__device__ int      d_eid[E2N + NG];             // CSR edge ids

// ---------------- helpers ----------------
__device__ __forceinline__ unsigned smem_u32(const void* p) {
    unsigned a;
    asm("{ .reg .u64 t; cvta.to.shared.u64 t, %1; cvt.u32.u64 %0, t; }"
        : "=r"(a) : "l"(p));
    return a;
}
__device__ __forceinline__ void ldsm4(unsigned* r, unsigned addr) {
    asm volatile("ldmatrix.sync.aligned.m8n8.x4.shared.b16 {%0,%1,%2,%3}, [%4];"
                 : "=r"(r[0]), "=r"(r[1]), "=r"(r[2]), "=r"(r[3]) : "r"(addr));
}
__device__ __forceinline__ void ldsm4t(unsigned* r, unsigned addr) {
    asm volatile("ldmatrix.sync.aligned.m8n8.x4.trans.shared.b16 {%0,%1,%2,%3}, [%4];"
                 : "=r"(r[0]), "=r"(r[1]), "=r"(r[2]), "=r"(r[3]) : "r"(addr));
}
__device__ __forceinline__ void mma16816(float* c, const unsigned* a, const unsigned* b) {
    asm volatile(
        "mma.sync.aligned.m16n8k16.row.col.f32.f16.f16.f32 "
        "{%0,%1,%2,%3},{%4,%5,%6,%7},{%8,%9},{%0,%1,%2,%3};"
        : "+f"(c[0]), "+f"(c[1]), "+f"(c[2]), "+f"(c[3])
        : "r"(a[0]), "r"(a[1]), "r"(a[2]), "r"(a[3]), "r"(b[0]), "r"(b[1]));
}
__device__ __forceinline__ uint2 cvt4h(float4 v) {
    __half2 h0 = __floats2half2_rn(v.x, v.y);
    __half2 h1 = __floats2half2_rn(v.z, v.w);
    uint2 r;
    r.x = *(unsigned*)&h0;
    r.y = *(unsigned*)&h1;
    return r;
}

// ---------------- fp16 tensor-core GEMM: C = [relu](A[M,K] @ B[K,N] (+ bias)) ----
// CTA tile 128x128, BK=32, 256 threads (8 warps 4x2), warp tile 32x64.
// A smem [m][k] (APAD=40 halfs), B smem [k][n] (BPAD=136 halfs, ldsm .trans).
// fp32->fp16 conversion at prefetch -> low register pressure, no spills.
// LS: additionally accumulate d_ls[row*4+head] += sum_c C[row,c]*Asc[head,c].
#define APAD 40
#define BPAD 136

template<bool RELU, bool BIAS, bool LS>
__global__ void __launch_bounds__(256, 2) hgemm_k(
    const float* __restrict__ A, const float* __restrict__ B,
    const float* __restrict__ bias, const float* __restrict__ Asc,
    float* __restrict__ Cout, int M, int N, int K)
{
    __shared__ __half smA[128 * APAD];
    __shared__ __half smB[32 * BPAD];

    const int t = threadIdx.x;
    const int lane = t & 31;
    const int w = t >> 5;
    const int wr = w >> 1;            // 0..3
    const int wc = w & 1;             // 0..1
    const int row0 = blockIdx.y * 128, col0 = blockIdx.x * 128;

    float acc[2][8][4];
#pragma unroll
    for (int i = 0; i < 2; i++)
#pragma unroll
        for (int j = 0; j < 8; j++)
#pragma unroll
            for (int q = 0; q < 4; q++) acc[i][j][q] = 0.f;

    const unsigned baseA = smem_u32(smA);
    const unsigned baseB = smem_u32(smB);

    // LDSM geometry
    const int arow_off = ((lane >> 3) & 1) * 8 + (lane & 7);  // A: m within 16-row frag
    const int achunk   = lane >> 4;                            // A: k chunk 0/1
    const int bk_off   = ((lane >> 3) & 1) * 8 + (lane & 7);  // B: k row within 16
    const int bn_off   = (lane >> 4) * 8;                      // B: n tile offset

    uint2 pa[4], pb[4];
    // prefetch tile 0 (fp32 -> fp16 immediately)
#pragma unroll
    for (int rep = 0; rep < 4; rep++) {
        int i = t + rep * 256;
        int r = i >> 3, kq = (i & 7) << 2;
        int gr = row0 + r;
        float4 va = (gr < M) ? *(const float4*)(A + (size_t)gr * K + kq)
                             : make_float4(0.f, 0.f, 0.f, 0.f);
        pa[rep] = cvt4h(va);
        int kk = i >> 5;              // rep0:0..7 rep1:8..15 ...
        int n4 = (i & 31) << 2;
        pb[rep] = cvt4h(*(const float4*)(B + (size_t)kk * N + col0 + n4));
    }

    for (int kt = 0; kt < K; kt += 32) {
        // ---- store prefetched tile to smem (vectorized) ----
#pragma unroll
        for (int rep = 0; rep < 4; rep++) {
            int i = t + rep * 256;
            int r = i >> 3, kq = (i & 7) << 2;
            *(uint2*)(smA + r * APAD + kq) = pa[rep];
            int kk = i >> 5;
            int n4 = (i & 31) << 2;
            *(uint2*)(smB + kk * BPAD + n4) = pb[rep];
        }
        __syncthreads();

        // ---- prefetch next ----
        if (kt + 32 < K) {
#pragma unroll
            for (int rep = 0; rep < 4; rep++) {
                int i = t + rep * 256;
                int r = i >> 3, kq = (i & 7) << 2;
                int gr = row0 + r;
                float4 va = (gr < M) ? *(const float4*)(A + (size_t)gr * K + kt + 32 + kq)
                                     : make_float4(0.f, 0.f, 0.f, 0.f);
                pa[rep] = cvt4h(va);
                int kk = i >> 5;
                int n4 = (i & 31) << 2;
                pb[rep] = cvt4h(*(const float4*)(B + (size_t)(kt + 32 + kk) * N + col0 + n4));
            }
        }

        // ---- compute 2 k16 steps ----
#pragma unroll
        for (int ks = 0; ks < 2; ks++) {
            unsigned af[2][4];
#pragma unroll
            for (int i = 0; i < 2; i++) {
                int row = wr * 32 + i * 16 + arow_off;
                ldsm4(af[i], baseA + (unsigned)(row * APAD + (2 * ks + achunk) * 8) * 2u);
            }
            unsigned bf[4][4];
#pragma unroll
            for (int j2 = 0; j2 < 4; j2++) {
                int krow = ks * 16 + bk_off;
                int ncol = wc * 64 + j2 * 16 + bn_off;
                ldsm4t(bf[j2], baseB + (unsigned)(krow * BPAD + ncol) * 2u);
            }
#pragma unroll
            for (int i = 0; i < 2; i++)
#pragma unroll
                for (int j = 0; j < 8; j++)
                    mma16816(acc[i][j], af[i], &bf[j >> 1][(j & 1) * 2]);
        }
        __syncthreads();
    }

    // ---- ls fusion: d_ls[row*4+head] += sum_c C[row,c] * Asc[head*CH + c] ----
    if (LS) {
        const float* ap = Asc + blockIdx.x * CH;   // this CTA covers exactly one head
        float part[2][2] = {{0.f, 0.f}, {0.f, 0.f}};
#pragma unroll
        for (int j = 0; j < 8; j++) {
            int cc = wc * 64 + j * 8 + (lane & 3) * 2;
            float a0 = __ldg(ap + cc), a1 = __ldg(ap + cc + 1);
#pragma unroll
            for (int i = 0; i < 2; i++) {
                part[i][0] += acc[i][j][0] * a0 + acc[i][j][1] * a1;
                part[i][1] += acc[i][j][2] * a0 + acc[i][j][3] * a1;
            }
        }
#pragma unroll
        for (int i = 0; i < 2; i++)
#pragma unroll
            for (int hf = 0; hf < 2; hf++) {
                float p = part[i][hf];
                p += __shfl_xor_sync(0xffffffffu, p, 1);
                p += __shfl_xor_sync(0xffffffffu, p, 2);
                if ((lane & 3) == 0) {
                    int gr = row0 + wr * 32 + i * 16 + hf * 8 + (lane >> 2);
                    if (gr < M) atomicAdd(&d_ls[gr * 4 + (int)blockIdx.x], p);
                }
            }
    }

    // ---- epilogue ----
#pragma unroll
    for (int i = 0; i < 2; i++) {
        int mr = row0 + wr * 32 + i * 16 + (lane >> 2);
#pragma unroll
        for (int j = 0; j < 8; j++) {
            int gc = col0 + wc * 64 + j * 8 + (lane & 3) * 2;
#pragma unroll
            for (int half = 0; half < 2; half++) {
                int gr = mr + half * 8;
                if (gr >= M) continue;
                float v0 = acc[i][j][half * 2 + 0];
                float v1 = acc[i][j][half * 2 + 1];
                if (BIAS) { v0 += bias[gc & (CH - 1)]; v1 += bias[(gc + 1) & (CH - 1)]; }
                if (RELU) { v0 = fmaxf(v0, 0.f); v1 = fmaxf(v1, 0.f); }
                *(float2*)(Cout + (size_t)gr * N + gc) = make_float2(v0, v1);
            }
        }
    }
}

// ---------------- BatchNorm ----------------
__global__ void zero_stats_k() {
    int i = blockIdx.x * blockDim.x + threadIdx.x;
    if (i < 2 * CH) d_stats[i] = 0.f;
}

__global__ void bn_stats_k(const float* __restrict__ h, int M) {
    int c = threadIdx.x;   // 128 threads
    int per = (M + gridDim.x - 1) / gridDim.x;
    int r0 = blockIdx.x * per;
    int r1 = r0 + per; if (r1 > M) r1 = M;
    float s = 0.f, ss = 0.f;
    for (int r = r0; r < r1; r++) {
        float v = h[(size_t)r * CH + c];
        s += v; ss += v * v;
    }
    atomicAdd(&d_stats[c], s);
    atomicAdd(&d_stats[CH + c], ss);
}

__global__ void bn_final_k(const float* __restrict__ gamma, const float* __restrict__ beta,
                           float invM) {
    int c = threadIdx.x;
    float mu  = d_stats[c] * invM;
    float var = d_stats[CH + c] * invM - mu * mu;
    float a = gamma[c] * rsqrtf(var + 1e-5f);
    d_aff[c] = a;
    d_aff[CH + c] = beta[c] - mu * a;
}

__global__ void bn_apply_k(float* __restrict__ h, int M) {
    int idx = blockIdx.x * blockDim.x + threadIdx.x;
    if (idx < M * CH) {
        int c = idx & (CH - 1);
        h[idx] = h[idx] * d_aff[c] + d_aff[CH + c];
    }
}

// ---------------- fold Wd with a_d ----------------
__global__ void fold_k(const float* __restrict__ W, const float* __restrict__ a) {
    int t = threadIdx.x;          // 512 threads
    int i = t >> 2, h = t & 3;
    float s = 0.f;
    for (int c = 0; c < CH; c++)
        s += W[(size_t)i * (NH * CH) + h * CH + c] * a[h * CH + c];
    d_fold[i * NH + h] = s;
}

// ---------------- zero d_ls (accumulated by GEMM epilogue) ----------------
__global__ void zero_ls_k(int N) {
    int i = blockIdx.x * blockDim.x + threadIdx.x;
    if (i < N * NH) d_ls[i] = 0.f;
}

// ---------------- ld[n,h] = sum_i g[n,i] * fold[i,h] ----------------
__global__ void ld_k(const float* __restrict__ g, int N) {
    int w = (blockIdx.x * blockDim.x + threadIdx.x) >> 5;
    int lane = threadIdx.x & 31;
    if (w >= N * NH) return;
    int n = w >> 2, h = w & 3;
    const float* gp = g + (size_t)n * CH;
    float s = 0.f;
    for (int c = lane; c < CH; c += 32) s += gp[c] * d_fold[c * NH + h];
    for (int o = 16; o; o >>= 1) s += __shfl_down_sync(0xffffffffu, s, o);
    if (!lane) d_ldv[w] = s;
}

// ---------------- CSR build ----------------
__global__ void initcsr_k() {
    int i = blockIdx.x * blockDim.x + threadIdx.x;
    if (i < NG) { d_cnt[i] = 0; d_cur[i] = 0; }
}

__global__ void hist_k(const int* __restrict__ src, const int* __restrict__ dst,
                       int E, int nloop) {
    int e = blockIdx.x * blockDim.x + threadIdx.x;
    if (e >= E + nloop) return;
    int d;
    if (e < E) {
        int s = src[e]; d = dst[e];
        if (s == d) return;                  // masked (remove_self_loops)
    } else d = e - E;
    atomicAdd(&d_cnt[d], 1);
}

// exclusive scan of d_cnt[0..NG) into d_off; d_off[NG] = total. One block, 1024 thr.
__global__ void scan_k() {
    __shared__ int ps[1024];
    int t = threadIdx.x;
    const int per = (NG + 1023) / 1024;
    int s0 = t * per, s1 = s0 + per; if (s1 > NG) s1 = NG; if (s0 > NG) s0 = NG;
    int sum = 0;
    for (int i = s0; i < s1; i++) sum += d_cnt[i];
    ps[t] = sum;
    __syncthreads();
    for (int o = 1; o < 1024; o <<= 1) {
        int v = (t >= o) ? ps[t - o] : 0;
        __syncthreads();
        ps[t] += v;
        __syncthreads();
    }
    int run = (t > 0) ? ps[t - 1] : 0;
    for (int i = s0; i < s1; i++) { d_off[i] = run; run += d_cnt[i]; }
    if (t == 1023) d_off[NG] = ps[1023];
}

__global__ void scatter_k(const int* __restrict__ src, const int* __restrict__ dst,
                          int E, int nloop) {
    int e = blockIdx.x * blockDim.x + threadIdx.x;
    if (e >= E + nloop) return;
    int d;
    if (e < E) {
        int s = src[e]; d = dst[e];
        if (s == d) return;
    } else d = e - E;
    int pos = atomicAdd(&d_cur[d], 1);
    d_eid[d_off[d] + pos] = e;
}

// ---------------- gather: warp per dst. out = base + bias + mean_h softmax-agg ----
__global__ void __launch_bounds__(256) gather_k(
    const int* __restrict__ src, int E,
    const float* __restrict__ base, const float* __restrict__ bias,
    float* __restrict__ out)
{
    int w = (blockIdx.x * blockDim.x + threadIdx.x) >> 5;
    int lane = threadIdx.x & 31;
    if (w >= NG) return;
    int o0 = d_off[w], o1 = d_off[w + 1];

    float ldh = (lane < 4) ? d_ldv[w * 4 + lane] : 0.f;

    // pass 1: per-head max of leaky_relu(ls+ld) over segment
    float mx = -1e30f;
    for (int i = o0; i < o1; i++) {
        int e = d_eid[i];
        int s = (e < E) ? src[e] : (e - E);
        if (lane < 4) {
            float x = d_ls[s * 4 + lane] + ldh;
            x = x > 0.f ? x : 0.2f * x;
            mx = fmaxf(mx, x);
        }
    }

    // pass 2: accumulate exp weights and weighted xs
    float4 a0 = make_float4(0.f,0.f,0.f,0.f), a1 = a0, a2 = a0, a3 = a0;
    float den = 0.f;
    for (int i = o0; i < o1; i++) {
        int e = d_eid[i];
        int s = (e < E) ? src[e] : (e - E);
        float p = 0.f;
        if (lane < 4) {
            float x = d_ls[s * 4 + lane] + ldh;
            x = x > 0.f ? x : 0.2f * x;
            p = expf(x - mx);
            den += p;
        }
        float p0 = __shfl_sync(0xffffffffu, p, 0);
        float p1 = __shfl_sync(0xffffffffu, p, 1);
        float p2 = __shfl_sync(0xffffffffu, p, 2);
        float p3 = __shfl_sync(0xffffffffu, p, 3);
        const float4* xp = (const float4*)(d_xs + (size_t)s * 512);
        float4 v;
        v = xp[lane];      a0.x += p0*v.x; a0.y += p0*v.y; a0.z += p0*v.z; a0.w += p0*v.w;
        v = xp[32 + lane]; a1.x += p1*v.x; a1.y += p1*v.y; a1.z += p1*v.z; a1.w += p1*v.w;
        v = xp[64 + lane]; a2.x += p2*v.x; a2.y += p2*v.y; a2.z += p2*v.z; a2.w += p2*v.w;
        v = xp[96 + lane]; a3.x += p3*v.x; a3.y += p3*v.y; a3.z += p3*v.z; a3.w += p3*v.w;
    }
    float d0 = __shfl_sync(0xffffffffu, den, 0);
    float d1 = __shfl_sync(0xffffffffu, den, 1);
    float d2 = __shfl_sync(0xffffffffu, den, 2);
    float d3 = __shfl_sync(0xffffffffu, den, 3);
    float i0 = (d0 > 0.f) ? 0.25f / d0 : 0.25f;
    float i1 = (d1 > 0.f) ? 0.25f / d1 : 0.25f;
    float i2 = (d2 > 0.f) ? 0.25f / d2 : 0.25f;
    float i3 = (d3 > 0.f) ? 0.25f / d3 : 0.25f;

    size_t idx = (size_t)w * CH + lane * 4;
    float4 bs = *(const float4*)(bias + lane * 4);
    float4 bv = *(const float4*)(base + idx);
    float4 r;
    r.x = bv.x + bs.x + a0.x*i0 + a1.x*i1 + a2.x*i2 + a3.x*i3;
    r.y = bv.y + bs.y + a0.y*i0 + a1.y*i1 + a2.y*i2 + a3.y*i3;
    r.z = bv.z + bs.z + a0.z*i0 + a1.z*i1 + a2.z*i2 + a3.z*i3;
    r.w = bv.w + bs.w + a0.w*i0 + a1.w*i1 + a2.w*i2 + a3.w*i3;
    *(float4*)(out + idx) = r;
}

// ---------------- host ----------------
extern "C" void kernel_launch(void* const* d_in, const int* in_sizes, int n_in,
                              void* d_out, int out_size) {
    const float* x_gene = (const float*)d_in[0];
    const float* x_dis  = (const float*)d_in[1];
    const int*   e1s    = (const int*)d_in[2];
    const int*   e1d    = (const int*)d_in[3];
    const int*   e2s    = (const int*)d_in[4];
    const int*   e2d    = (const int*)d_in[5];
    const float* Wg = (const float*)d_in[6],  *bg = (const float*)d_in[7];
    const float* gg = (const float*)d_in[8],  *betag = (const float*)d_in[9];
    const float* Wd = (const float*)d_in[10], *bd = (const float*)d_in[11];
    const float* gd = (const float*)d_in[12], *betad = (const float*)d_in[13];
    const float* W1s = (const float*)d_in[14], *W1d = (const float*)d_in[15];
    const float* a1s = (const float*)d_in[16], *a1d = (const float*)d_in[17];
    const float* b1  = (const float*)d_in[18];
    const float* W2s = (const float*)d_in[19], *W2d = (const float*)d_in[20];
    const float* a2s = (const float*)d_in[21], *a2d = (const float*)d_in[22];
    const float* b2  = (const float*)d_in[23];

    float* outg = (float*)d_out;
    float* outd = outg + (size_t)NG * CH;

    float *pg = nullptr, *pxs = nullptr;
    cudaGetSymbolAddress((void**)&pg,  d_g);
    cudaGetSymbolAddress((void**)&pxs, d_xs);

    const int TB = 256;
    // ---- encode gene ----
    zero_stats_k<<<1, 256>>>();
    hgemm_k<true, true, false><<<dim3(1, (NG + 127) / 128), 256>>>(x_gene, Wg, bg, nullptr, pg, NG, CH, FG);
    bn_stats_k<<<128, 128>>>(pg, NG);
    bn_final_k<<<1, 128>>>(gg, betag, 1.f / NG);
    bn_apply_k<<<(NG * CH + TB - 1) / TB, TB>>>(pg, NG);
    // ---- encode dis (directly into output region) ----
    zero_stats_k<<<1, 256>>>();
    hgemm_k<true, true, false><<<dim3(1, (ND + 127) / 128), 256>>>(x_dis, Wd, bd, nullptr, outd, ND, CH, FD);
    bn_stats_k<<<128, 128>>>(outd, ND);
    bn_final_k<<<1, 128>>>(gd, betad, 1.f / ND);
    bn_apply_k<<<(ND * CH + TB - 1) / TB, TB>>>(outd, ND);

    // ---- relation 1: dis -> gene (in-place update of pg) ----
    fold_k<<<1, 512>>>(W1d, a1d);
    zero_ls_k<<<(ND * NH + TB - 1) / TB, TB>>>(ND);
    hgemm_k<false, false, true><<<dim3((NH * CH) / 128, (ND + 127) / 128), 256>>>(outd, W1s, nullptr, a1s, pxs, ND, NH * CH, CH);
    ld_k<<<(NG * NH * 32 + TB - 1) / TB, TB>>>(pg, NG);
    initcsr_k<<<(NG + TB - 1) / TB, TB>>>();
    int tot1 = E1N + ND;
    hist_k<<<(tot1 + TB - 1) / TB, TB>>>(e1s, e1d, E1N, ND);
    scan_k<<<1, 1024>>>();
    scatter_k<<<(tot1 + TB - 1) / TB, TB>>>(e1s, e1d, E1N, ND);
    gather_k<<<(NG * 32 + TB - 1) / TB, TB>>>(e1s, E1N, pg, b1, pg);

    // ---- relation 2: gene -> gene (writes final outg) ----
    fold_k<<<1, 512>>>(W2d, a2d);
    zero_ls_k<<<(NG * NH + TB - 1) / TB, TB>>>(NG);
    hgemm_k<false, false, true><<<dim3((NH * CH) / 128, (NG + 127) / 128), 256>>>(pg, W2s, nullptr, a2s, pxs, NG, NH * CH, CH);
    ld_k<<<(NG * NH * 32 + TB - 1) / TB, TB>>>(pg, NG);
    initcsr_k<<<(NG + TB - 1) / TB, TB>>>();
    int tot2 = E2N + NG;
    hist_k<<<(tot2 + TB - 1) / TB, TB>>>(e2s, e2d, E2N, NG);
    scan_k<<<1, 1024>>>();
    scatter_k<<<(tot2 + TB - 1) / TB, TB>>>(e2s, e2d, E2N, NG);
    gather_k<<<(NG * 32 + TB - 1) / TB, TB>>>(e2s, E2N, pg, b2, outg);
}